// round 9
// baseline (speedup 1.0000x reference)
#include <cuda_runtime.h>
#include <math.h>

#define N_NODES 100000
#define N_EDGES 3200000
#define IN_CH   256
#define HC      128   // HEADS*OUT_CH flattened
#define OUT_CH  64
#define NEG_SLOPE 0.2f

typedef unsigned long long ull;

// ---------------- scratch ----------------
__device__ float g_x[(size_t)N_NODES * HC];      // projected features, 51.2 MB
__device__ float4 g_att[N_NODES];                // (a_src0, a_src1, a_dst0, a_dst1)
__device__ int g_count[N_NODES];
__device__ int g_offset[N_NODES];
__device__ int g_cursor[N_NODES];
__device__ int g_sorted_src[N_EDGES];            // src idx sorted by dst

__device__ __forceinline__ float lrelu(float v) {
    return fmaxf(v, NEG_SLOPE * v);
}

// packed dual-fp32 FMA (sm_103a FFMA2): exact fp32 on both lanes
__device__ __forceinline__ ull fma2(ull a, ull b, ull c) {
    ull d;
    asm("fma.rn.f32x2 %0, %1, %2, %3;" : "=l"(d) : "l"(a), "l"(b), "l"(c));
    return d;
}
__device__ __forceinline__ ull pack_dup(float v) {
    unsigned u = __float_as_uint(v);
    return (ull)u | ((ull)u << 32);
}
__device__ __forceinline__ float lo_f(ull p) { return __uint_as_float((unsigned)p); }
__device__ __forceinline__ float hi_f(ull p) { return __uint_as_float((unsigned)(p >> 32)); }

// ---------------- zero counts ----------------
__global__ void zero_counts_kernel() {
    int i = blockIdx.x * blockDim.x + threadIdx.x;
    if (i < N_NODES) g_count[i] = 0;
}

// ------ SGEMM x = z@W with FFMA2 + fused attention-dot epilogue ------------
#define BM 128
#define BN 128
#define BK 16

__global__ __launch_bounds__(256) void gemm_kernel(const float* __restrict__ Z,
                                                   const float* __restrict__ Wm,
                                                   const float* __restrict__ att_src,
                                                   const float* __restrict__ att_dst) {
    __shared__ ull   As2[2][BK][BM];  // A value duplicated into both 32-bit halves
    __shared__ float Bs[2][BK][BN];
    int tid = threadIdx.x;
    int row0 = blockIdx.x * BM;

    int a_r = tid >> 2;            // 0..63
    int a_c = (tid & 3) << 2;      // 0,4,8,12
    int b_r = tid >> 5;            // 0..7
    int b_c = (tid & 31) << 2;     // 0..124

    int tx = tid & 15;             // column group
    int ty = tid >> 4;             // row group

    ull acc2[8][4];
#pragma unroll
    for (int i = 0; i < 8; i++)
#pragma unroll
        for (int j = 0; j < 4; j++) acc2[i][j] = 0ull;

    float4 av[2], bv[2];
#pragma unroll
    for (int i = 0; i < 2; i++) {
        int r = row0 + a_r + i * 64;
        av[i] = make_float4(0.f, 0.f, 0.f, 0.f);
        if (r < N_NODES) av[i] = *(const float4*)&Z[(size_t)r * IN_CH + a_c];
        bv[i] = *(const float4*)&Wm[(size_t)(b_r + i * 8) * BN + b_c];
    }
#pragma unroll
    for (int i = 0; i < 2; i++) {
        As2[0][a_c + 0][a_r + i * 64] = pack_dup(av[i].x);
        As2[0][a_c + 1][a_r + i * 64] = pack_dup(av[i].y);
        As2[0][a_c + 2][a_r + i * 64] = pack_dup(av[i].z);
        As2[0][a_c + 3][a_r + i * 64] = pack_dup(av[i].w);
        *(float4*)&Bs[0][b_r + i * 8][b_c] = bv[i];
    }
    __syncthreads();

    const int NK = IN_CH / BK;     // 16
    for (int kt = 0; kt < NK; kt++) {
        int cur = kt & 1;
        int nxt = cur ^ 1;
        if (kt + 1 < NK) {
            int k0 = (kt + 1) * BK;
#pragma unroll
            for (int i = 0; i < 2; i++) {
                int r = row0 + a_r + i * 64;
                av[i] = make_float4(0.f, 0.f, 0.f, 0.f);
                if (r < N_NODES) av[i] = *(const float4*)&Z[(size_t)r * IN_CH + k0 + a_c];
                bv[i] = *(const float4*)&Wm[(size_t)(k0 + b_r + i * 8) * BN + b_c];
            }
        }
#pragma unroll
        for (int k = 0; k < BK; k++) {
            ull a2[8], b2[4];
            const ull* bsrow = (const ull*)&Bs[cur][k][0];
#pragma unroll
            for (int i = 0; i < 4; i++) {
                a2[i]     = As2[cur][k][ty * 4 + i];
                a2[i + 4] = As2[cur][k][64 + ty * 4 + i];
            }
            b2[0] = bsrow[tx * 2];
            b2[1] = bsrow[tx * 2 + 1];
            b2[2] = bsrow[32 + tx * 2];
            b2[3] = bsrow[33 + tx * 2];
#pragma unroll
            for (int i = 0; i < 8; i++)
#pragma unroll
                for (int j = 0; j < 4; j++)
                    acc2[i][j] = fma2(a2[i], b2[j], acc2[i][j]);
        }
        if (kt + 1 < NK) {
#pragma unroll
            for (int i = 0; i < 2; i++) {
                As2[nxt][a_c + 0][a_r + i * 64] = pack_dup(av[i].x);
                As2[nxt][a_c + 1][a_r + i * 64] = pack_dup(av[i].y);
                As2[nxt][a_c + 2][a_r + i * 64] = pack_dup(av[i].z);
                As2[nxt][a_c + 3][a_r + i * 64] = pack_dup(av[i].w);
                *(float4*)&Bs[nxt][b_r + i * 8][b_c] = bv[i];
            }
        }
        __syncthreads();
    }

    // attention weight slices for this thread's 8 columns
    float4 as_lo = __ldg((const float4*)&att_src[tx * 4]);
    float4 as_hi = __ldg((const float4*)&att_src[64 + tx * 4]);
    float4 ad_lo = __ldg((const float4*)&att_dst[tx * 4]);
    float4 ad_hi = __ldg((const float4*)&att_dst[64 + tx * 4]);

#pragma unroll
    for (int i = 0; i < 8; i++) {
        float c0 = lo_f(acc2[i][0]), c1 = hi_f(acc2[i][0]);
        float c2 = lo_f(acc2[i][1]), c3 = hi_f(acc2[i][1]);
        float c4 = lo_f(acc2[i][2]), c5 = hi_f(acc2[i][2]);
        float c6 = lo_f(acc2[i][3]), c7 = hi_f(acc2[i][3]);
        int r = row0 + ((i < 4) ? (ty * 4 + i) : (64 + ty * 4 + (i - 4)));

        // per-head attention partial dots (head0 = cols 0..63, head1 = 64..127)
        float ps0 = c0 * as_lo.x + c1 * as_lo.y + c2 * as_lo.z + c3 * as_lo.w;
        float ps1 = c4 * as_hi.x + c5 * as_hi.y + c6 * as_hi.z + c7 * as_hi.w;
        float pd0 = c0 * ad_lo.x + c1 * ad_lo.y + c2 * ad_lo.z + c3 * ad_lo.w;
        float pd1 = c4 * ad_hi.x + c5 * ad_hi.y + c6 * ad_hi.z + c7 * ad_hi.w;
        // reduce across the 16 tx lanes (tx = low 4 lane bits)
#pragma unroll
        for (int off = 8; off; off >>= 1) {
            ps0 += __shfl_xor_sync(0xffffffffu, ps0, off);
            ps1 += __shfl_xor_sync(0xffffffffu, ps1, off);
            pd0 += __shfl_xor_sync(0xffffffffu, pd0, off);
            pd1 += __shfl_xor_sync(0xffffffffu, pd1, off);
        }
        if (r < N_NODES) {
            float* orow = &g_x[(size_t)r * HC];
            *(float4*)&orow[tx * 4]      = make_float4(c0, c1, c2, c3);
            *(float4*)&orow[64 + tx * 4] = make_float4(c4, c5, c6, c7);
            if (tx == 0)
                g_att[r] = make_float4(ps0, ps1, pd0, pd1);
        }
    }
}

// ------- histogram of dst (edge_index int32, row-split [src(E) | dst(E)]) --
__global__ void hist_kernel(const int* __restrict__ ei) {
    int e = blockIdx.x * blockDim.x + threadIdx.x;
    if (e < N_EDGES) {
        int d = __ldg(&ei[N_EDGES + e]);
        if ((unsigned)d < (unsigned)N_NODES)
            atomicAdd(&g_count[d], 1);
    }
}

// ---------------- 1-block, 2-pass exclusive scan of counts ----------------
__global__ void scan_kernel() {
    __shared__ int sh[1024];
    int t = threadIdx.x;
    const int CH = (N_NODES + 1023) / 1024;   // 98
    int begin = t * CH;
    int end = begin + CH; if (end > N_NODES) end = N_NODES;
    int sum = 0;
    for (int i = begin; i < end; i++) sum += g_count[i];
    sh[t] = sum;
    __syncthreads();
    for (int off = 1; off < 1024; off <<= 1) {
        int v = (t >= off) ? sh[t - off] : 0;
        __syncthreads();
        sh[t] += v;
        __syncthreads();
    }
    int run = (t == 0) ? 0 : sh[t - 1];
    for (int i = begin; i < end; i++) {
        g_offset[i] = run;
        g_cursor[i] = run;
        run += g_count[i];
    }
}

// ---------------- counting-sort scatter of src indices ----------------
__global__ void scatter_kernel(const int* __restrict__ ei) {
    int e = blockIdx.x * blockDim.x + threadIdx.x;
    if (e < N_EDGES) {
        int d = __ldg(&ei[N_EDGES + e]);
        int s = __ldg(&ei[e]);
        if ((unsigned)d < (unsigned)N_NODES && (unsigned)s < (unsigned)N_NODES) {
            int pos = atomicAdd(&g_cursor[d], 1);
            g_sorted_src[pos] = s;
        }
    }
}

// ------ aggregation: single pass, un-normalized softmax, 4-way unrolled ----
__global__ __launch_bounds__(256) void aggregate_kernel(const float* __restrict__ bias,
                                                        float* __restrict__ out) {
    int warp = (blockIdx.x * blockDim.x + threadIdx.x) >> 5;
    if (warp >= N_NODES) return;
    int lane = threadIdx.x & 31;
    int d = warp;

    float4 attv = g_att[d];                 // (as0, as1, ad0, ad1)
    int h = lane >> 4;
    float adst = h ? attv.w : attv.z;

    const float4* x4 = (const float4*)g_x;
    const float2* att2 = (const float2*)g_att;

    // self-loop contribution
    float w0 = __expf(lrelu((h ? attv.y : attv.x) + adst));
    float s0 = w0;
    float4 xs = x4[(size_t)d * 32 + lane];
    float4 acc0 = make_float4(w0 * xs.x, w0 * xs.y, w0 * xs.z, w0 * xs.w);
    float s1 = 0.f;
    float4 acc1 = make_float4(0.f, 0.f, 0.f, 0.f);

    int base = g_offset[d];
    int cnt  = g_count[d];

    int i = 0;
    for (; i + 4 <= cnt; i += 4) {
        int sa = g_sorted_src[base + i];
        int sb = g_sorted_src[base + i + 1];
        int sc = g_sorted_src[base + i + 2];
        int sd = g_sorted_src[base + i + 3];
        float2 aa = att2[(size_t)sa * 2];
        float2 ab = att2[(size_t)sb * 2];
        float2 ac = att2[(size_t)sc * 2];
        float2 ad = att2[(size_t)sd * 2];
        float4 xa = x4[(size_t)sa * 32 + lane];
        float4 xb = x4[(size_t)sb * 32 + lane];
        float4 xc = x4[(size_t)sc * 32 + lane];
        float4 xd = x4[(size_t)sd * 32 + lane];

        float wa = __expf(lrelu((h ? aa.y : aa.x) + adst));
        float wb = __expf(lrelu((h ? ab.y : ab.x) + adst));
        float wc = __expf(lrelu((h ? ac.y : ac.x) + adst));
        float wd = __expf(lrelu((h ? ad.y : ad.x) + adst));

        s0 += wa;
        acc0.x += wa * xa.x; acc0.y += wa * xa.y;
        acc0.z += wa * xa.z; acc0.w += wa * xa.w;
        s1 += wb;
        acc1.x += wb * xb.x; acc1.y += wb * xb.y;
        acc1.z += wb * xb.z; acc1.w += wb * xb.w;
        s0 += wc;
        acc0.x += wc * xc.x; acc0.y += wc * xc.y;
        acc0.z += wc * xc.z; acc0.w += wc * xc.w;
        s1 += wd;
        acc1.x += wd * xd.x; acc1.y += wd * xd.y;
        acc1.z += wd * xd.z; acc1.w += wd * xd.w;
    }
    for (; i < cnt; i++) {
        int sa = g_sorted_src[base + i];
        float2 aa = att2[(size_t)sa * 2];
        float4 xa = x4[(size_t)sa * 32 + lane];
        float wa = __expf(lrelu((h ? aa.y : aa.x) + adst));
        s0 += wa;
        acc0.x += wa * xa.x; acc0.y += wa * xa.y;
        acc0.z += wa * xa.z; acc0.w += wa * xa.w;
    }

    float s = s0 + s1;
    float4 acc = make_float4(acc0.x + acc1.x, acc0.y + acc1.y,
                             acc0.z + acc1.z, acc0.w + acc1.w);

    float inv = 1.0f / (2.0f * s);          // /s then mean over 2 heads
    acc.x *= inv; acc.y *= inv; acc.z *= inv; acc.w *= inv;

    // combine heads: lane j (head0) + lane j+16 (head1)
    float ox = __shfl_down_sync(0xffffffffu, acc.x, 16);
    float oy = __shfl_down_sync(0xffffffffu, acc.y, 16);
    float oz = __shfl_down_sync(0xffffffffu, acc.z, 16);
    float ow = __shfl_down_sync(0xffffffffu, acc.w, 16);
    if (lane < 16) {
        float4 b = __ldg((const float4*)&bias[lane * 4]);
        float4 r = make_float4(acc.x + ox + b.x, acc.y + oy + b.y,
                               acc.z + oz + b.z, acc.w + ow + b.w);
        *(float4*)&out[(size_t)d * OUT_CH + lane * 4] = r;
    }
}

// ---------------- launch ----------------
extern "C" void kernel_launch(void* const* d_in, const int* in_sizes, int n_in,
                              void* d_out, int out_size) {
    const float* z       = (const float*)d_in[0];
    const int*   ei      = (const int*)d_in[1];     // int32, row-split [src(E) | dst(E)]
    const float* Wm      = (const float*)d_in[2];
    const float* att_src = (const float*)d_in[3];
    const float* att_dst = (const float*)d_in[4];
    const float* bias    = (const float*)d_in[5];
    float* out = (float*)d_out;

    zero_counts_kernel<<<(N_NODES + 255) / 256, 256>>>();               // launch 0
    gemm_kernel<<<(N_NODES + BM - 1) / BM, 256>>>(z, Wm, att_src, att_dst); // 1
    hist_kernel<<<(N_EDGES + 255) / 256, 256>>>(ei);                    // 2
    scan_kernel<<<1, 1024>>>();                                         // 3
    scatter_kernel<<<(N_EDGES + 255) / 256, 256>>>(ei);                 // 4
    aggregate_kernel<<<(N_NODES * 32 + 255) / 256, 256>>>(bias, out);   // 5 (ncu -s 5)
}

// round 10
// speedup vs baseline: 1.5295x; 1.5295x over previous
#include <cuda_runtime.h>
#include <math.h>

#define N_NODES 100000
#define N_EDGES 3200000
#define IN_CH   256
#define HC      128   // HEADS*OUT_CH flattened
#define OUT_CH  64
#define NEG_SLOPE 0.2f

#define SCAN_BLOCK 512
#define N_CHUNKS ((N_NODES + SCAN_BLOCK - 1) / SCAN_BLOCK)   // 196

// ---------------- scratch ----------------
__device__ float g_x[(size_t)N_NODES * HC];      // projected features, 51.2 MB
__device__ float4 g_att[N_NODES];                // (a_src0, a_src1, a_dst0, a_dst1)
__device__ int g_count[N_NODES];
__device__ int g_offset[N_NODES];
__device__ int g_cursor[N_NODES];
__device__ int g_partial[N_CHUNKS];
__device__ int g_sorted_src[N_EDGES];            // src idx sorted by dst

__device__ __forceinline__ float lrelu(float v) {
    return fmaxf(v, NEG_SLOPE * v);
}

// ---------------- zero counts ----------------
__global__ void zero_counts_kernel() {
    int i = blockIdx.x * blockDim.x + threadIdx.x;
    if (i < N_NODES) g_count[i] = 0;
}

// ---------------- SGEMM: x = z @ W, double-buffered smem pipeline ----------
#define BM 128
#define BN 128
#define BK 16

__global__ __launch_bounds__(256) void gemm_kernel(const float* __restrict__ Z,
                                                   const float* __restrict__ Wm) {
    __shared__ float As[2][BK][BM];   // transposed A tile
    __shared__ float Bs[2][BK][BN];
    int tid = threadIdx.x;
    int row0 = blockIdx.x * BM;

    int a_r = tid >> 2;            // 0..63
    int a_c = (tid & 3) << 2;      // 0,4,8,12
    int b_r = tid >> 5;            // 0..7
    int b_c = (tid & 31) << 2;     // 0..124

    int tx = tid & 15;             // column group
    int ty = tid >> 4;             // row group

    float acc[8][8];
#pragma unroll
    for (int i = 0; i < 8; i++)
#pragma unroll
        for (int j = 0; j < 8; j++) acc[i][j] = 0.f;

    float4 av[2], bv[2];
#pragma unroll
    for (int i = 0; i < 2; i++) {
        int r = row0 + a_r + i * 64;
        av[i] = make_float4(0.f, 0.f, 0.f, 0.f);
        if (r < N_NODES) av[i] = *(const float4*)&Z[(size_t)r * IN_CH + a_c];
        bv[i] = *(const float4*)&Wm[(size_t)(b_r + i * 8) * BN + b_c];
    }
#pragma unroll
    for (int i = 0; i < 2; i++) {
        As[0][a_c + 0][a_r + i * 64] = av[i].x;
        As[0][a_c + 1][a_r + i * 64] = av[i].y;
        As[0][a_c + 2][a_r + i * 64] = av[i].z;
        As[0][a_c + 3][a_r + i * 64] = av[i].w;
        *(float4*)&Bs[0][b_r + i * 8][b_c] = bv[i];
    }
    __syncthreads();

    const int NK = IN_CH / BK;     // 16
    for (int kt = 0; kt < NK; kt++) {
        int cur = kt & 1;
        int nxt = cur ^ 1;
        if (kt + 1 < NK) {
            int k0 = (kt + 1) * BK;
#pragma unroll
            for (int i = 0; i < 2; i++) {
                int r = row0 + a_r + i * 64;
                av[i] = make_float4(0.f, 0.f, 0.f, 0.f);
                if (r < N_NODES) av[i] = *(const float4*)&Z[(size_t)r * IN_CH + k0 + a_c];
                bv[i] = *(const float4*)&Wm[(size_t)(k0 + b_r + i * 8) * BN + b_c];
            }
        }
#pragma unroll
        for (int k = 0; k < BK; k++) {
            float a[8], b[8];
#pragma unroll
            for (int i = 0; i < 4; i++) {
                a[i]     = As[cur][k][ty * 4 + i];
                a[i + 4] = As[cur][k][64 + ty * 4 + i];
            }
#pragma unroll
            for (int j = 0; j < 4; j++) {
                b[j]     = Bs[cur][k][tx * 4 + j];
                b[j + 4] = Bs[cur][k][64 + tx * 4 + j];
            }
#pragma unroll
            for (int i = 0; i < 8; i++)
#pragma unroll
                for (int j = 0; j < 8; j++)
                    acc[i][j] += a[i] * b[j];
        }
        if (kt + 1 < NK) {
#pragma unroll
            for (int i = 0; i < 2; i++) {
                As[nxt][a_c + 0][a_r + i * 64] = av[i].x;
                As[nxt][a_c + 1][a_r + i * 64] = av[i].y;
                As[nxt][a_c + 2][a_r + i * 64] = av[i].z;
                As[nxt][a_c + 3][a_r + i * 64] = av[i].w;
                *(float4*)&Bs[nxt][b_r + i * 8][b_c] = bv[i];
            }
        }
        __syncthreads();
    }

#pragma unroll
    for (int i = 0; i < 8; i++) {
        int r = row0 + ((i < 4) ? (ty * 4 + i) : (64 + ty * 4 + (i - 4)));
        if (r < N_NODES) {
            float* orow = &g_x[(size_t)r * HC];
            *(float4*)&orow[tx * 4]      = make_float4(acc[i][0], acc[i][1], acc[i][2], acc[i][3]);
            *(float4*)&orow[64 + tx * 4] = make_float4(acc[i][4], acc[i][5], acc[i][6], acc[i][7]);
        }
    }
}

// ---------------- per-node attention dots: a_src / a_dst per head ----------
__global__ void att_kernel(const float* __restrict__ att_src,
                           const float* __restrict__ att_dst) {
    int warp = (blockIdx.x * blockDim.x + threadIdx.x) >> 5;
    if (warp >= N_NODES) return;
    int lane = threadIdx.x & 31;

    float4 xv  = *(const float4*)&g_x[(size_t)warp * HC + lane * 4];
    float4 as4 = __ldg((const float4*)&att_src[lane * 4]);  // flat (H*C)=128
    float4 ad4 = __ldg((const float4*)&att_dst[lane * 4]);

    float ps = xv.x * as4.x + xv.y * as4.y + xv.z * as4.z + xv.w * as4.w;
    float pd = xv.x * ad4.x + xv.y * ad4.y + xv.z * ad4.z + xv.w * ad4.w;
#pragma unroll
    for (int off = 8; off; off >>= 1) {
        ps += __shfl_xor_sync(0xffffffffu, ps, off);
        pd += __shfl_xor_sync(0xffffffffu, pd, off);
    }
    // convergent cross-half shuffles
    float ps16 = __shfl_sync(0xffffffffu, ps, 16);  // head-1 src dot
    float pd16 = __shfl_sync(0xffffffffu, pd, 16);  // head-1 dst dot
    if (lane == 0) {
        g_att[warp] = make_float4(ps, ps16, pd, pd16);
    }
}

// ------- histogram of dst (edge_index int32, row-split [src(E) | dst(E)]) --
__global__ void hist_kernel(const int* __restrict__ ei) {
    int e = blockIdx.x * blockDim.x + threadIdx.x;
    if (e < N_EDGES) {
        int d = __ldg(&ei[N_EDGES + e]);
        if ((unsigned)d < (unsigned)N_NODES)
            atomicAdd(&g_count[d], 1);
    }
}

// ---------- decoupled scan, stage 1: per-chunk sums (196 blocks) ----------
__global__ __launch_bounds__(SCAN_BLOCK) void scan_partial_kernel() {
    __shared__ int sh[SCAN_BLOCK / 32];
    int i = blockIdx.x * SCAN_BLOCK + threadIdx.x;
    int v = (i < N_NODES) ? g_count[i] : 0;
#pragma unroll
    for (int off = 16; off; off >>= 1) v += __shfl_xor_sync(0xffffffffu, v, off);
    int wid = threadIdx.x >> 5;
    if ((threadIdx.x & 31) == 0) sh[wid] = v;
    __syncthreads();
    if (wid == 0) {
        int t = (threadIdx.x < SCAN_BLOCK / 32) ? sh[threadIdx.x] : 0;
#pragma unroll
        for (int off = 8; off; off >>= 1) t += __shfl_xor_sync(0xffffffffu, t, off);
        if (threadIdx.x == 0) g_partial[blockIdx.x] = t;
    }
}

// ---------- stage 2: exclusive scan of 196 partials (1 small block) -------
__global__ __launch_bounds__(256) void scan_top_kernel() {
    __shared__ int sh[256];
    int t = threadIdx.x;
    int v = (t < N_CHUNKS) ? g_partial[t] : 0;
    sh[t] = v;
    __syncthreads();
    for (int off = 1; off < 256; off <<= 1) {
        int u = (t >= off) ? sh[t - off] : 0;
        __syncthreads();
        sh[t] += u;
        __syncthreads();
    }
    if (t < N_CHUNKS) g_partial[t] = sh[t] - v;   // exclusive
}

// ---------- stage 3: local exclusive scan + chunk offset (196 blocks) -----
__global__ __launch_bounds__(SCAN_BLOCK) void scan_final_kernel() {
    __shared__ int sh[SCAN_BLOCK];
    int t = threadIdx.x;
    int i = blockIdx.x * SCAN_BLOCK + t;
    int c = (i < N_NODES) ? g_count[i] : 0;
    sh[t] = c;
    __syncthreads();
    for (int off = 1; off < SCAN_BLOCK; off <<= 1) {
        int u = (t >= off) ? sh[t - off] : 0;
        __syncthreads();
        sh[t] += u;
        __syncthreads();
    }
    if (i < N_NODES) {
        int off = g_partial[blockIdx.x] + sh[t] - c;  // exclusive prefix
        g_offset[i] = off;
        g_cursor[i] = off;
    }
}

// ---------------- counting-sort scatter of src indices ----------------
__global__ void scatter_kernel(const int* __restrict__ ei) {
    int e = blockIdx.x * blockDim.x + threadIdx.x;
    if (e < N_EDGES) {
        int d = __ldg(&ei[N_EDGES + e]);
        int s = __ldg(&ei[e]);
        if ((unsigned)d < (unsigned)N_NODES && (unsigned)s < (unsigned)N_NODES) {
            int pos = atomicAdd(&g_cursor[d], 1);
            g_sorted_src[pos] = s;
        }
    }
}

// ------ aggregation: single pass, un-normalized softmax, 2-way unrolled ----
// Logits are lrelu of ~N(0,2) dots; exp is safe in fp32 (overflow at 88).
__global__ __launch_bounds__(256) void aggregate_kernel(const float* __restrict__ bias,
                                                        float* __restrict__ out) {
    int warp = (blockIdx.x * blockDim.x + threadIdx.x) >> 5;
    if (warp >= N_NODES) return;
    int lane = threadIdx.x & 31;
    int d = warp;

    float4 attv = g_att[d];                 // (as0, as1, ad0, ad1)
    int h = lane >> 4;
    float adst = h ? attv.w : attv.z;

    const float4* x4 = (const float4*)g_x;
    const float2* att2 = (const float2*)g_att;

    // self-loop contribution
    float w0 = __expf(lrelu((h ? attv.y : attv.x) + adst));
    float s0 = w0;
    float4 xs = x4[(size_t)d * 32 + lane];
    float4 acc0 = make_float4(w0 * xs.x, w0 * xs.y, w0 * xs.z, w0 * xs.w);
    float s1 = 0.f;
    float4 acc1 = make_float4(0.f, 0.f, 0.f, 0.f);

    int base = g_offset[d];
    int cnt  = g_count[d];

    int i = 0;
    for (; i + 2 <= cnt; i += 2) {
        int sa = g_sorted_src[base + i];
        int sb = g_sorted_src[base + i + 1];
        float2 aa = att2[(size_t)sa * 2];
        float2 ab = att2[(size_t)sb * 2];
        float4 xa = x4[(size_t)sa * 32 + lane];
        float4 xb = x4[(size_t)sb * 32 + lane];

        float wa = __expf(lrelu((h ? aa.y : aa.x) + adst));
        float wb = __expf(lrelu((h ? ab.y : ab.x) + adst));

        s0 += wa;
        acc0.x += wa * xa.x; acc0.y += wa * xa.y;
        acc0.z += wa * xa.z; acc0.w += wa * xa.w;
        s1 += wb;
        acc1.x += wb * xb.x; acc1.y += wb * xb.y;
        acc1.z += wb * xb.z; acc1.w += wb * xb.w;
    }
    if (i < cnt) {
        int sa = g_sorted_src[base + i];
        float2 aa = att2[(size_t)sa * 2];
        float4 xa = x4[(size_t)sa * 32 + lane];
        float wa = __expf(lrelu((h ? aa.y : aa.x) + adst));
        s0 += wa;
        acc0.x += wa * xa.x; acc0.y += wa * xa.y;
        acc0.z += wa * xa.z; acc0.w += wa * xa.w;
    }

    float s = s0 + s1;
    float4 acc = make_float4(acc0.x + acc1.x, acc0.y + acc1.y,
                             acc0.z + acc1.z, acc0.w + acc1.w);

    float inv = 1.0f / (2.0f * s);          // /s then mean over 2 heads
    acc.x *= inv; acc.y *= inv; acc.z *= inv; acc.w *= inv;

    // combine heads: lane j (head0) + lane j+16 (head1)
    float ox = __shfl_down_sync(0xffffffffu, acc.x, 16);
    float oy = __shfl_down_sync(0xffffffffu, acc.y, 16);
    float oz = __shfl_down_sync(0xffffffffu, acc.z, 16);
    float ow = __shfl_down_sync(0xffffffffu, acc.w, 16);
    if (lane < 16) {
        float4 b = __ldg((const float4*)&bias[lane * 4]);
        float4 r = make_float4(acc.x + ox + b.x, acc.y + oy + b.y,
                               acc.z + oz + b.z, acc.w + ow + b.w);
        *(float4*)&out[(size_t)d * OUT_CH + lane * 4] = r;
    }
}

// ---------------- launch ----------------
extern "C" void kernel_launch(void* const* d_in, const int* in_sizes, int n_in,
                              void* d_out, int out_size) {
    const float* z       = (const float*)d_in[0];
    const int*   ei      = (const int*)d_in[1];     // int32, row-split [src(E) | dst(E)]
    const float* Wm      = (const float*)d_in[2];
    const float* att_src = (const float*)d_in[3];
    const float* att_dst = (const float*)d_in[4];
    const float* bias    = (const float*)d_in[5];
    float* out = (float*)d_out;

    zero_counts_kernel<<<(N_NODES + 255) / 256, 256>>>();               // 0
    hist_kernel<<<(N_EDGES + 255) / 256, 256>>>(ei);                    // 1
    scan_partial_kernel<<<N_CHUNKS, SCAN_BLOCK>>>();                    // 2
    gemm_kernel<<<(N_NODES + BM - 1) / BM, 256>>>(z, Wm);               // 3 (profiled)
    scan_top_kernel<<<1, 256>>>();                                      // 4
    scan_final_kernel<<<N_CHUNKS, SCAN_BLOCK>>>();                      // 5
    scatter_kernel<<<(N_EDGES + 255) / 256, 256>>>(ei);                 // 6
    att_kernel<<<(N_NODES * 32 + 255) / 256, 256>>>(att_src, att_dst);  // 7
    aggregate_kernel<<<(N_NODES * 32 + 255) / 256, 256>>>(bias, out);   // 8
}